// round 11
// baseline (speedup 1.0000x reference)
#include <cuda_runtime.h>
#include <math.h>
#include <stdint.h>

// Problem constants
#define MTOK  4096      // B*T tokens
#define DD    1024      // model dim
#define INNER 2048      // expanded dim
#define SST   64        // state dim
#define HIDD  4096      // expert hidden
#define NE    4         // experts
#define TT    2048      // seq len
#define NB    2         // batch
#define NDBC  192       // fused dt|B|C output width

// ---------------- scratch (static device memory; no allocations) -------------
__device__ float g_h1 [(size_t)MTOK*DD];
__device__ float g_xz [(size_t)MTOK*2*INNER];
__device__ float g_xm [(size_t)MTOK*INNER];
__device__ float g_dt [(size_t)MTOK*SST];
__device__ float g_Bm [(size_t)MTOK*SST];
__device__ float g_Cm [(size_t)MTOK*SST];
__device__ float g_y  [(size_t)MTOK*SST];
__device__ float g_u  [(size_t)MTOK*INNER];
__device__ float g_x2 [(size_t)MTOK*DD];
__device__ float g_h2 [(size_t)MTOK*DD];
__device__ float g_hid[(size_t)MTOK*HIDD];
__device__ float g_wfull[(size_t)MTOK*NE];
__device__ float g_wdbc[(size_t)INNER*NDBC];
__device__ int   g_idx[NE*MTOK];
__device__ float g_wl [NE*MTOK];
__device__ int   g_cnt[NE];
// tf32-rounded weight copies (GEMM B operands only)
__device__ float g_ipw [(size_t)DD*2*INNER];
__device__ float g_s2iw[(size_t)SST*INNER];
__device__ float g_ow  [(size_t)INNER*DD];
__device__ float g_ew1 [(size_t)NE*DD*HIDD];
__device__ float g_ew2 [(size_t)NE*HIDD*DD];

__device__ __forceinline__ float sigmoidf_(float v){ return 1.0f/(1.0f+expf(-v)); }

// round-to-nearest tf32 (RNA), as uint bits / as float
__device__ __forceinline__ uint32_t tf32u(float x){
    uint32_t u; asm("cvt.rna.tf32.f32 %0, %1;" : "=r"(u) : "f"(x));
    return u;
}
__device__ __forceinline__ float tf32r(float x){ return __uint_as_float(tf32u(x)); }

__device__ __forceinline__ void mma_tf32(float4& d, const uint32_t* a, const uint32_t* b){
    asm volatile("mma.sync.aligned.m16n8k8.row.col.f32.tf32.tf32.f32 "
        "{%0,%1,%2,%3}, {%4,%5,%6,%7}, {%8,%9}, {%0,%1,%2,%3};"
        : "+f"(d.x), "+f"(d.y), "+f"(d.z), "+f"(d.w)
        : "r"(a[0]), "r"(a[1]), "r"(a[2]), "r"(a[3]), "r"(b[0]), "r"(b[1]));
}

// cp.async 16B with zero-fill when pred is false (src-size = 0)
__device__ __forceinline__ void cpa16(uint32_t dst, const void* src, bool pred){
    int sz = pred ? 16 : 0;
    asm volatile("cp.async.cg.shared.global [%0], [%1], 16, %2;\n"
                 :: "r"(dst), "l"(src), "r"(sz));
}
__device__ __forceinline__ void cpa_commit(){ asm volatile("cp.async.commit_group;\n"); }
__device__ __forceinline__ void cpa_wait1(){ asm volatile("cp.async.wait_group 1;\n"); }

// ---------------- epilogue functors (ALL outputs full fp32) -------------------
struct EpBias {
    const float* bias; float* C; int ldc;
    __device__ __forceinline__ void store(int r,int c,float acc) const {
        C[(size_t)r*ldc + c] = acc + bias[c];
    }
};
struct EpDBC {           // fused dt|Bm|Cm epilogue by column range
    const float *dtb,*bpb,*cpb; float *dt,*Bm,*Cm;
    __device__ __forceinline__ void store(int r,int c,float acc) const {
        if (c < 64)       dt[(size_t)r*SST + c]        = sigmoidf_(acc + dtb[c]);
        else if (c < 128) Bm[(size_t)r*SST + (c-64)]   = acc + bpb[c-64];
        else              Cm[(size_t)r*SST + (c-128)]  = acc + cpb[c-128];
    }
};
struct EpGelu {          // exact gelu, writes compacted hid rows
    const float* bias; float* C; int ldc;
    __device__ __forceinline__ void store(int r,int c,float acc) const {
        float v = acc + bias[c];
        C[(size_t)r*ldc + c] = 0.5f*v*(1.0f + erff(v*0.70710678118654752f));
    }
};
struct EpS2I {           // + s2i_b + D*x_main, * sigmoid(gate)
    const float* bias; const float* Dp; const float* xm; const float* xz; float* C;
    __device__ __forceinline__ void store(int r,int c,float acc) const {
        float v = acc + bias[c];
        v = fmaf(Dp[c], xm[(size_t)r*INNER + c], v);
        v *= sigmoidf_(xz[(size_t)r*(2*INNER) + INNER + c]);
        C[(size_t)r*INNER + c] = v;
    }
};
struct EpOut {           // + out_b + residual x ; dual store (x2 and d_out)
    const float* bias; const float* resid; float* C; float* out;
    __device__ __forceinline__ void store(int r,int c,float acc) const {
        float v = acc + bias[c] + resid[(size_t)r*DD + c];
        C[(size_t)r*DD + c] = v;
        out[(size_t)r*DD + c] = v;
    }
};
struct EpMoE2 {          // scatter: out[tok] += w * (acc + b2)
    const float* bias; const int* idx; const float* wl; float* out;
    __device__ __forceinline__ void store(int r,int c,float acc) const {
        int t = idx[r];
        out[(size_t)t*DD + c] += wl[r]*(acc + bias[c]);
    }
};

// ---------------- tf32 tensor-core GEMM, 2-stage cp.async, BK=32 -------------
// A row-major [M,K] full fp32 (optional row gather) — cvt.rna at fragment load.
// B row-major [K,N] MUST be tf32-pre-rounded — raw bits into mma.
// A staged [m][k] LDA=36, B staged [k][n] LDB=136: conflict-free fragment LDS.
// Dynamic SMEM: 2*128*36*4 + 2*32*136*4 = 71,680 B.
#define GEMM_SMEM 71680
template<class Ep>
__global__ void __launch_bounds__(256)
gemm_tf32(const float* __restrict__ A, const float* __restrict__ B,
          int M, int N, int K,
          const int* __restrict__ mcnt,   // if non-null: device row count
          const int* __restrict__ ridx,   // if non-null: gather A rows
          Ep ep)
{
    constexpr int BM=128, BN=128, BK=32;
    constexpr int LDA=36, LDB=136;
    extern __shared__ float sm_[];
    float (*As)[BM][LDA] = reinterpret_cast<float(*)[BM][LDA]>(sm_);
    float (*Bs)[BK][LDB] = reinterpret_cast<float(*)[BK][LDB]>(sm_ + 2*BM*LDA);
    constexpr uint32_t A_STG = BM*LDA*4;   // bytes per A stage
    constexpr uint32_t B_STG = BK*LDB*4;   // bytes per B stage

    int Mr = mcnt ? *mcnt : M;
    int rb = blockIdx.y*BM;
    if (rb >= Mr) return;
    int nb = blockIdx.x*BN;

    int tid  = threadIdx.x;
    int lane = tid & 31, wid = tid >> 5;
    int wm = wid & 3, wn = wid >> 2;
    int g  = lane >> 2, tg = lane & 3;

    // A: thread covers one row, 16 floats starting at (tid&1)*16
    int a_row = tid >> 1;
    int a_k0  = (tid & 1) * 16;
    bool a_ok = (rb + a_row) < Mr;
    const float* a_src = A;
    if (a_ok) {
        int ar = ridx ? ridx[rb + a_row] : (rb + a_row);
        a_src = A + (size_t)ar*K + a_k0;
    }
    uint32_t a_dst0 = (uint32_t)__cvta_generic_to_shared(&As[0][a_row][a_k0]);

    // B: 4 chunks per thread, linear chunk id c = tid + 256*j
    const float* b_src[4]; bool b_ok[4]; uint32_t b_dst0[4];
    #pragma unroll
    for (int j=0;j<4;j++) {
        int c = tid + 256*j;
        int br = c >> 5;
        int bc = (c & 31) * 4;
        b_ok[j]  = (nb + bc) < N;
        b_src[j] = B + (size_t)br*N + nb + bc;
        b_dst0[j] = (uint32_t)__cvta_generic_to_shared(&Bs[0][br][bc]);
    }

    float4 acc[2][8];
    #pragma unroll
    for (int i=0;i<2;i++)
        #pragma unroll
        for (int j=0;j<8;j++) acc[i][j] = make_float4(0.f,0.f,0.f,0.f);

    int KT = K/BK;

    // prologue: tile 0 → stage 0
    #pragma unroll
    for (int q=0;q<4;q++) cpa16(a_dst0 + q*16, a_src + q*4, a_ok);
    #pragma unroll
    for (int j=0;j<4;j++) cpa16(b_dst0[j], b_src[j], b_ok[j]);
    cpa_commit();

    for (int kt=0; kt<KT; kt++) {
        int s = kt & 1;
        if (kt+1 < KT) {
            uint32_t ns = (uint32_t)((kt+1) & 1);
            const float* as = a_src + (size_t)(kt+1)*BK;
            #pragma unroll
            for (int q=0;q<4;q++) cpa16(a_dst0 + ns*A_STG + q*16, as + q*4, a_ok);
            size_t boff = (size_t)(kt+1)*BK*N;
            #pragma unroll
            for (int j=0;j<4;j++) cpa16(b_dst0[j] + ns*B_STG, b_src[j] + boff, b_ok[j]);
        }
        cpa_commit();
        cpa_wait1();          // tile kt resident; tile kt+1 may be in flight
        __syncthreads();

        #pragma unroll
        for (int ks=0; ks<BK; ks+=8) {
            uint32_t af[2][4];
            #pragma unroll
            for (int i=0;i<2;i++) {
                int m0 = wm*32 + i*16 + g;
                af[i][0] = tf32u(As[s][m0  ][ks+tg  ]);
                af[i][1] = tf32u(As[s][m0+8][ks+tg  ]);
                af[i][2] = tf32u(As[s][m0  ][ks+tg+4]);
                af[i][3] = tf32u(As[s][m0+8][ks+tg+4]);
            }
            uint32_t bf[8][2];
            #pragma unroll
            for (int j=0;j<8;j++) {
                int n0 = wn*64 + j*8 + g;
                bf[j][0] = __float_as_uint(Bs[s][ks+tg  ][n0]);   // pre-rounded
                bf[j][1] = __float_as_uint(Bs[s][ks+tg+4][n0]);
            }
            #pragma unroll
            for (int i=0;i<2;i++)
                #pragma unroll
                for (int j=0;j<8;j++) mma_tf32(acc[i][j], af[i], bf[j]);
        }
        __syncthreads();
    }

    #pragma unroll
    for (int i=0;i<2;i++) {
        int r0 = rb + wm*32 + i*16 + g;
        int r1 = r0 + 8;
        #pragma unroll
        for (int j=0;j<8;j++) {
            int c0 = nb + wn*64 + j*8 + tg*2;
            if (r0 < Mr) {
                if (c0   < N) ep.store(r0, c0,   acc[i][j].x);
                if (c0+1 < N) ep.store(r0, c0+1, acc[i][j].y);
            }
            if (r1 < Mr) {
                if (c0   < N) ep.store(r1, c0,   acc[i][j].z);
                if (c0+1 < N) ep.store(r1, c0+1, acc[i][j].w);
            }
        }
    }
}

// ---------------- tf32-round a weight array (float4 vectorized) --------------
__global__ void round_w_kernel(const float4* __restrict__ src, float4* __restrict__ dst, int n4)
{
    int i = blockIdx.x*blockDim.x + threadIdx.x;
    if (i >= n4) return;
    float4 v = src[i];
    v.x = tf32r(v.x); v.y = tf32r(v.y); v.z = tf32r(v.z); v.w = tf32r(v.w);
    dst[i] = v;
}

// ---------------- concat dt|B|C weights into [INNER, 192] (rounded) ----------
__global__ void concat_dbc_kernel(const float* __restrict__ dtw,
                                  const float* __restrict__ bpw,
                                  const float* __restrict__ cpw,
                                  float* __restrict__ W)
{
    int i = blockIdx.x*blockDim.x + threadIdx.x;
    if (i >= INNER*NDBC) return;
    int r = i / NDBC, c = i % NDBC;
    float v;
    if (c < 64)       v = dtw[r*SST + c];
    else if (c < 128) v = bpw[r*SST + (c-64)];
    else              v = cpw[r*SST + (c-128)];
    W[i] = tf32r(v);
}

// ---------------- rmsnorm (row of 1024), eps 1e-6; full fp32 output ----------
__global__ void rmsnorm_kernel(const float* __restrict__ x, const float* __restrict__ w,
                               float* __restrict__ o)
{
    int r = blockIdx.x;
    const float* xr = x + (size_t)r*DD;
    float s = 0.f;
    for (int i=threadIdx.x; i<DD; i+=blockDim.x) { float v = xr[i]; s = fmaf(v,v,s); }
    #pragma unroll
    for (int off=16; off; off>>=1) s += __shfl_xor_sync(0xffffffffu, s, off);
    __shared__ float red[8];
    int wid = threadIdx.x>>5, lane = threadIdx.x&31;
    if (lane==0) red[wid]=s;
    __syncthreads();
    if (threadIdx.x==0) {
        float t=0.f;
        for (int i=0;i<(int)(blockDim.x>>5);i++) t += red[i];
        red[0] = rsqrtf(t/(float)DD + 1e-6f);
    }
    __syncthreads();
    float nr = red[0];
    float* orow = o + (size_t)r*DD;
    for (int i=threadIdx.x; i<DD; i+=blockDim.x) orow[i] = xr[i]*nr*w[i];
}

// ---------------- causal depthwise conv (K=3) + silu, 4-channel vectorized ---
__global__ void conv_silu_kernel(const float* __restrict__ xz, const float* __restrict__ cw,
                                 const float* __restrict__ cb, float* __restrict__ xm)
{
    int idx = blockIdx.x*blockDim.x + threadIdx.x;       // over MTOK*INNER/4
    if (idx >= MTOK*INNER/4) return;
    int c4  = idx & (INNER/4 - 1);                       // 512 groups
    int tok = idx >> 9;
    int t   = tok & (TT-1);
    int c   = c4*4;
    const float* base = xz + (size_t)tok*(2*INNER) + c;   // x_main half
    float4 zero = make_float4(0.f,0.f,0.f,0.f);
    float4 x0 = *reinterpret_cast<const float4*>(base);
    float4 x1 = (t>=1) ? *reinterpret_cast<const float4*>(base - 2*INNER) : zero;
    float4 x2 = (t>=2) ? *reinterpret_cast<const float4*>(base - 4*INNER) : zero;
    float4 w0 = *reinterpret_cast<const float4*>(cw + c*3);
    float4 w1 = *reinterpret_cast<const float4*>(cw + c*3 + 4);
    float4 w2 = *reinterpret_cast<const float4*>(cw + c*3 + 8);
    float4 bb = *reinterpret_cast<const float4*>(cb + c);
    float v0 = fmaf(w0.x,x2.x, fmaf(w0.y,x1.x, w0.z*x0.x)) + bb.x;
    float v1 = fmaf(w0.w,x2.y, fmaf(w1.x,x1.y, w1.y*x0.y)) + bb.y;
    float v2 = fmaf(w1.z,x2.z, fmaf(w1.w,x1.z, w2.x*x0.z)) + bb.z;
    float v3 = fmaf(w2.y,x2.w, fmaf(w2.z,x1.w, w2.w*x0.w)) + bb.w;
    float4 r;
    r.x = v0 * sigmoidf_(v0);
    r.y = v1 * sigmoidf_(v1);
    r.z = v2 * sigmoidf_(v2);
    r.w = v3 * sigmoidf_(v3);
    *reinterpret_cast<float4*>(xm + (size_t)tok*INNER + c) = r;
}

// ---------------- selective-state scan (serial over T) -----------------------
__global__ void scan_kernel(const float* __restrict__ dt, const float* __restrict__ Bv,
                            const float* __restrict__ Cv, float* __restrict__ y)
{
    int tid = threadIdx.x;          // 128 = NB * SST
    if (tid >= NB*SST) return;
    int b = tid >> 6, s = tid & 63;
    float st = 0.f;
    size_t off = ((size_t)b*TT)*SST + s;
    for (int t=0; t<TT; t++, off += SST) {
        float d = dt[off], bb = Bv[off], cc = Cv[off];
        st = fmaf(d, bb - st, st);           // (1-d)*st + d*b
        y[off] = cc*st;
    }
}

// ---------------- layernorm over 64 (one warp per token), eps 1e-5 -----------
__global__ void ln64_kernel(float* __restrict__ y)
{
    int gw = (blockIdx.x*blockDim.x + threadIdx.x) >> 5;
    if (gw >= MTOK) return;
    int lane = threadIdx.x & 31;
    float* r = y + (size_t)gw*SST;
    float v0 = r[lane], v1 = r[lane+32];
    float sum = v0 + v1;
    #pragma unroll
    for (int off=16; off; off>>=1) sum += __shfl_xor_sync(0xffffffffu, sum, off);
    float mu = sum * (1.0f/64.0f);
    float d0 = v0-mu, d1 = v1-mu;
    float vs = d0*d0 + d1*d1;
    #pragma unroll
    for (int off=16; off; off>>=1) vs += __shfl_xor_sync(0xffffffffu, vs, off);
    float nr = rsqrtf(vs*(1.0f/64.0f) + 1e-5f);
    r[lane]    = d0*nr;
    r[lane+32] = d1*nr;
}

// ---------------- gating: logits, top-2 softmax → dense weights --------------
__global__ void gate_kernel(const float* __restrict__ h2, const float* __restrict__ gw,
                            const float* __restrict__ gb, float* __restrict__ wfull)
{
    int gwarp = (blockIdx.x*blockDim.x + threadIdx.x) >> 5;
    if (gwarp >= MTOK) return;
    int lane = threadIdx.x & 31;
    float a0=0,a1=0,a2=0,a3=0;
    const float* hr = h2 + (size_t)gwarp*DD;
    for (int d=lane; d<DD; d+=32) {
        float h = hr[d];
        float4 w = *reinterpret_cast<const float4*>(gw + d*4);
        a0 = fmaf(h,w.x,a0); a1 = fmaf(h,w.y,a1);
        a2 = fmaf(h,w.z,a2); a3 = fmaf(h,w.w,a3);
    }
    #pragma unroll
    for (int off=16; off; off>>=1) {
        a0 += __shfl_xor_sync(0xffffffffu,a0,off);
        a1 += __shfl_xor_sync(0xffffffffu,a1,off);
        a2 += __shfl_xor_sync(0xffffffffu,a2,off);
        a3 += __shfl_xor_sync(0xffffffffu,a3,off);
    }
    if (lane==0) {
        float l[4] = {a0+gb[0], a1+gb[1], a2+gb[2], a3+gb[3]};
        int i0 = 0;
        for (int e=1;e<4;e++) if (l[e] > l[i0]) i0 = e;       // strict: earliest on tie
        int i1 = -1;
        for (int e=0;e<4;e++) if (e!=i0 && (i1<0 || l[e] > l[i1])) i1 = e;
        float e1 = expf(l[i1]-l[i0]);
        float p0 = 1.0f/(1.0f+e1);
        float p1 = e1/(1.0f+e1);
        float* wr = wfull + (size_t)gwarp*NE;
        wr[0]=0.f; wr[1]=0.f; wr[2]=0.f; wr[3]=0.f;
        wr[i0]=p0; wr[i1]=p1;
    }
}

// ---------------- deterministic per-expert token lists -----------------------
__global__ void build_lists_kernel(const float* __restrict__ wfull,
                                   int* __restrict__ idx, float* __restrict__ wl,
                                   int* __restrict__ cnt)
{
    int e = blockIdx.x;
    __shared__ int pref[1024];
    __shared__ int base;
    if (threadIdx.x==0) base = 0;
    __syncthreads();
    for (int chunk=0; chunk<MTOK/1024; chunk++) {
        int t = chunk*1024 + threadIdx.x;
        float w = wfull[(size_t)t*NE + e];
        int pred = (w > 0.f) ? 1 : 0;
        pref[threadIdx.x] = pred;
        __syncthreads();
        for (int off=1; off<1024; off<<=1) {
            int v = (threadIdx.x >= off) ? pref[threadIdx.x-off] : 0;
            __syncthreads();
            pref[threadIdx.x] += v;
            __syncthreads();
        }
        if (pred) {
            int pos = base + pref[threadIdx.x] - 1;
            idx[e*MTOK + pos] = t;
            wl [e*MTOK + pos] = w;
        }
        __syncthreads();
        if (threadIdx.x==0) base += pref[1023];
        __syncthreads();
    }
    if (threadIdx.x==0) cnt[e] = base;
}

// =============================================================================
extern "C" void kernel_launch(void* const* d_in, const int* in_sizes, int n_in,
                              void* d_out, int out_size)
{
    const float* x    = (const float*)d_in[0];
    const float* n1w  = (const float*)d_in[1];
    const float* n2w  = (const float*)d_in[2];
    const float* ipw  = (const float*)d_in[3];
    const float* ipb  = (const float*)d_in[4];
    const float* cw   = (const float*)d_in[5];
    const float* cb   = (const float*)d_in[6];
    const float* dtw  = (const float*)d_in[7];
    const float* dtb  = (const float*)d_in[8];
    const float* bpw  = (const float*)d_in[9];
    const float* bpb  = (const float*)d_in[10];
    const float* cpw  = (const float*)d_in[11];
    const float* cpb  = (const float*)d_in[12];
    const float* s2iw = (const float*)d_in[13];
    const float* s2ib = (const float*)d_in[14];
    const float* Dp   = (const float*)d_in[15];
    const float* ow   = (const float*)d_in[16];
    const float* obp  = (const float*)d_in[17];
    const float* gw   = (const float*)d_in[18];
    const float* gb   = (const float*)d_in[19];
    const float* ew1  = (const float*)d_in[20];
    const float* eb1  = (const float*)d_in[21];
    const float* ew2  = (const float*)d_in[22];
    const float* eb2  = (const float*)d_in[23];
    float* out = (float*)d_out;

    float *h1,*xz,*xm,*dt,*Bm,*Cm,*y,*u,*x2,*h2,*hid,*wfull,*wl,*wdbc;
    float *ripw,*rs2iw,*row_,*rew1,*rew2;
    int *idx,*cnt;
    cudaGetSymbolAddress((void**)&h1,   g_h1);
    cudaGetSymbolAddress((void**)&xz,   g_xz);
    cudaGetSymbolAddress((void**)&xm,   g_xm);
    cudaGetSymbolAddress((void**)&dt,   g_dt);
    cudaGetSymbolAddress((void**)&Bm,   g_Bm);
    cudaGetSymbolAddress((void**)&Cm,   g_Cm);
    cudaGetSymbolAddress((void**)&y,    g_y);
    cudaGetSymbolAddress((void**)&u,    g_u);
    cudaGetSymbolAddress((void**)&x2,   g_x2);
    cudaGetSymbolAddress((void**)&h2,   g_h2);
    cudaGetSymbolAddress((void**)&hid,  g_hid);
    cudaGetSymbolAddress((void**)&wfull,g_wfull);
    cudaGetSymbolAddress((void**)&wl,   g_wl);
    cudaGetSymbolAddress((void**)&wdbc, g_wdbc);
    cudaGetSymbolAddress((void**)&idx,  g_idx);
    cudaGetSymbolAddress((void**)&cnt,  g_cnt);
    cudaGetSymbolAddress((void**)&ripw, g_ipw);
    cudaGetSymbolAddress((void**)&rs2iw,g_s2iw);
    cudaGetSymbolAddress((void**)&row_, g_ow);
    cudaGetSymbolAddress((void**)&rew1, g_ew1);
    cudaGetSymbolAddress((void**)&rew2, g_ew2);

    // opt-in SMEM for all gemm instantiations (idempotent)
    cudaFuncSetAttribute(gemm_tf32<EpBias>, cudaFuncAttributeMaxDynamicSharedMemorySize, GEMM_SMEM);
    cudaFuncSetAttribute(gemm_tf32<EpDBC>,  cudaFuncAttributeMaxDynamicSharedMemorySize, GEMM_SMEM);
    cudaFuncSetAttribute(gemm_tf32<EpS2I>,  cudaFuncAttributeMaxDynamicSharedMemorySize, GEMM_SMEM);
    cudaFuncSetAttribute(gemm_tf32<EpOut>,  cudaFuncAttributeMaxDynamicSharedMemorySize, GEMM_SMEM);
    cudaFuncSetAttribute(gemm_tf32<EpGelu>, cudaFuncAttributeMaxDynamicSharedMemorySize, GEMM_SMEM);
    cudaFuncSetAttribute(gemm_tf32<EpMoE2>, cudaFuncAttributeMaxDynamicSharedMemorySize, GEMM_SMEM);

    // ---- weight pre-rounding (tf32 RNA); B operands only ----
    round_w_kernel<<<(DD*2*INNER/4 + 255)/256, 256>>>((const float4*)ipw,  (float4*)ripw,  DD*2*INNER/4);
    round_w_kernel<<<(SST*INNER/4   + 255)/256, 256>>>((const float4*)s2iw, (float4*)rs2iw, SST*INNER/4);
    round_w_kernel<<<(INNER*DD/4    + 255)/256, 256>>>((const float4*)ow,   (float4*)row_,  INNER*DD/4);
    round_w_kernel<<<(NE*DD*HIDD/4  + 255)/256, 256>>>((const float4*)ew1,  (float4*)rew1,  NE*DD*HIDD/4);
    round_w_kernel<<<(NE*HIDD*DD/4  + 255)/256, 256>>>((const float4*)ew2,  (float4*)rew2,  NE*HIDD*DD/4);
    concat_dbc_kernel<<<(INNER*NDBC + 255)/256, 256>>>(dtw, bpw, cpw, wdbc);

    // ---- mixer ----
    rmsnorm_kernel<<<MTOK, 256>>>(x, n1w, h1);

    gemm_tf32<EpBias><<<dim3(2*INNER/128, MTOK/128), 256, GEMM_SMEM>>>(
        h1, ripw, MTOK, 2*INNER, DD, nullptr, nullptr, EpBias{ipb, xz, 2*INNER});

    conv_silu_kernel<<<(MTOK*INNER/4)/256, 256>>>(xz, cw, cb, xm);

    gemm_tf32<EpDBC><<<dim3(2, MTOK/128), 256, GEMM_SMEM>>>(
        xm, wdbc, MTOK, NDBC, INNER, nullptr, nullptr,
        EpDBC{dtb, bpb, cpb, dt, Bm, Cm});

    scan_kernel<<<1, 128>>>(dt, Bm, Cm, y);
    ln64_kernel<<<MTOK/4, 128>>>(y);

    gemm_tf32<EpS2I><<<dim3(INNER/128, MTOK/128), 256, GEMM_SMEM>>>(
        y, rs2iw, MTOK, INNER, SST, nullptr, nullptr, EpS2I{s2ib, Dp, xm, xz, u});

    gemm_tf32<EpOut><<<dim3(DD/128, MTOK/128), 256, GEMM_SMEM>>>(
        u, row_, MTOK, DD, INNER, nullptr, nullptr, EpOut{obp, x, x2, out});

    // ---- MoE ----
    rmsnorm_kernel<<<MTOK, 256>>>(x2, n2w, h2);
    gate_kernel<<<MTOK/8, 256>>>(h2, gw, gb, wfull);
    build_lists_kernel<<<NE, 1024>>>(wfull, idx, wl, cnt);

    for (int e=0; e<NE; e++) {
        gemm_tf32<EpGelu><<<dim3(HIDD/128, MTOK/128), 256, GEMM_SMEM>>>(
            h2, rew1 + (size_t)e*DD*HIDD, MTOK, HIDD, DD,
            cnt + e, idx + e*MTOK,
            EpGelu{eb1 + (size_t)e*HIDD, hid, HIDD});
        gemm_tf32<EpMoE2><<<dim3(DD/128, MTOK/128), 256, GEMM_SMEM>>>(
            hid, rew2 + (size_t)e*HIDD*DD, MTOK, DD, HIDD,
            cnt + e, nullptr,
            EpMoE2{eb2 + (size_t)e*DD, idx + e*MTOK, wl + e*MTOK, out});
    }
}

// round 13
// speedup vs baseline: 1.1274x; 1.1274x over previous
#include <cuda_runtime.h>
#include <math.h>
#include <stdint.h>

// Problem constants
#define MTOK  4096      // B*T tokens
#define DD    1024      // model dim
#define INNER 2048      // expanded dim
#define SST   64        // state dim
#define HIDD  4096      // expert hidden
#define NE    4         // experts
#define TT    2048      // seq len
#define NB    2         // batch
#define NDBC  192       // fused dt|B|C output width

// ---------------- scratch (static device memory; no allocations) -------------
__device__ float g_h1 [(size_t)MTOK*DD];
__device__ float g_xz [(size_t)MTOK*2*INNER];
__device__ float g_xm [(size_t)MTOK*INNER];
__device__ float g_dt [(size_t)MTOK*SST];
__device__ float g_Bm [(size_t)MTOK*SST];
__device__ float g_Cm [(size_t)MTOK*SST];
__device__ float g_y  [(size_t)MTOK*SST];
__device__ float g_u  [(size_t)MTOK*INNER];
__device__ float g_x2 [(size_t)MTOK*DD];
__device__ float g_h2 [(size_t)MTOK*DD];
__device__ float g_hid[(size_t)NE*MTOK*HIDD];   // per-expert hidden slices
__device__ float g_wfull[(size_t)MTOK*NE];
__device__ float g_wdbc[(size_t)INNER*NDBC];
__device__ int   g_idx[NE*MTOK];
__device__ float g_wl [NE*MTOK];
__device__ int   g_cnt[NE];

__device__ __forceinline__ float sigmoidf_(float v){ return 1.0f/(1.0f+expf(-v)); }

// round-to-nearest tf32 (RNA), as uint bits
__device__ __forceinline__ uint32_t tf32u(float x){
    uint32_t u; asm("cvt.rna.tf32.f32 %0, %1;" : "=r"(u) : "f"(x));
    return u;
}

__device__ __forceinline__ void mma_tf32(float4& d, const uint32_t* a, const uint32_t* b){
    asm volatile("mma.sync.aligned.m16n8k8.row.col.f32.tf32.tf32.f32 "
        "{%0,%1,%2,%3}, {%4,%5,%6,%7}, {%8,%9}, {%0,%1,%2,%3};"
        : "+f"(d.x), "+f"(d.y), "+f"(d.z), "+f"(d.w)
        : "r"(a[0]), "r"(a[1]), "r"(a[2]), "r"(a[3]), "r"(b[0]), "r"(b[1]));
}

// cp.async 16B with zero-fill when pred is false (src-size = 0)
__device__ __forceinline__ void cpa16(uint32_t dst, const void* src, bool pred){
    int sz = pred ? 16 : 0;
    asm volatile("cp.async.cg.shared.global [%0], [%1], 16, %2;\n"
                 :: "r"(dst), "l"(src), "r"(sz));
}
__device__ __forceinline__ void cpa_commit(){ asm volatile("cp.async.commit_group;\n"); }
__device__ __forceinline__ void cpa_wait1(){ asm volatile("cp.async.wait_group 1;\n"); }

// ---------------- epilogue functors (all outputs full fp32) -------------------
struct EpBias {
    const float* bias; float* C; int ldc;
    __device__ __forceinline__ void setz(int){}
    __device__ __forceinline__ void store(int r,int c,float acc) const {
        C[(size_t)r*ldc + c] = acc + bias[c];
    }
};
struct EpDBC {           // fused dt|Bm|Cm epilogue by column range
    const float *dtb,*bpb,*cpb; float *dt,*Bm,*Cm;
    __device__ __forceinline__ void setz(int){}
    __device__ __forceinline__ void store(int r,int c,float acc) const {
        if (c < 64)       dt[(size_t)r*SST + c]        = sigmoidf_(acc + dtb[c]);
        else if (c < 128) Bm[(size_t)r*SST + (c-64)]   = acc + bpb[c-64];
        else              Cm[(size_t)r*SST + (c-128)]  = acc + cpb[c-128];
    }
};
struct EpGelu {          // exact gelu, per-expert hid slice via setz
    const float* bias; float* C; int ldc;
    __device__ __forceinline__ void setz(int e){
        bias += (size_t)e*HIDD;
        C    += (size_t)e*MTOK*HIDD;
    }
    __device__ __forceinline__ void store(int r,int c,float acc) const {
        float v = acc + bias[c];
        C[(size_t)r*ldc + c] = 0.5f*v*(1.0f + erff(v*0.70710678118654752f));
    }
};
struct EpS2I {           // + s2i_b + D*x_main, * sigmoid(gate)
    const float* bias; const float* Dp; const float* xm; const float* xz; float* C;
    __device__ __forceinline__ void setz(int){}
    __device__ __forceinline__ void store(int r,int c,float acc) const {
        float v = acc + bias[c];
        v = fmaf(Dp[c], xm[(size_t)r*INNER + c], v);
        v *= sigmoidf_(xz[(size_t)r*(2*INNER) + INNER + c]);
        C[(size_t)r*INNER + c] = v;
    }
};
struct EpOut {           // + out_b + residual x ; dual store (x2 and d_out)
    const float* bias; const float* resid; float* C; float* out;
    __device__ __forceinline__ void setz(int){}
    __device__ __forceinline__ void store(int r,int c,float acc) const {
        float v = acc + bias[c] + resid[(size_t)r*DD + c];
        C[(size_t)r*DD + c] = v;
        out[(size_t)r*DD + c] = v;
    }
};
struct EpMoE2 {          // scatter: out[tok] += w * (acc + b2); atomic (2 adds/elem)
    const float* bias; const int* idx; const float* wl; float* out;
    __device__ __forceinline__ void setz(int e){
        bias += (size_t)e*DD;
        idx  += (size_t)e*MTOK;
        wl   += (size_t)e*MTOK;
    }
    __device__ __forceinline__ void store(int r,int c,float acc) const {
        int t = idx[r];
        atomicAdd(&out[(size_t)t*DD + c], wl[r]*(acc + bias[c]));
    }
};

// ---------------- tf32 tensor-core GEMM, 2-stage cp.async, BK=32 -------------
// A row-major [M,K], B row-major [K,N], both full fp32 — cvt.rna at fragment load.
// blockIdx.z = expert slice (strides aZ/bZ/listZ; 0 for single-matrix GEMMs).
// A staged [m][k] LDA=36, B staged [k][n] LDB=136: conflict-free fragment LDS.
// Dynamic SMEM: 2*128*36*4 + 2*32*136*4 = 71,680 B.
#define GEMM_SMEM 71680
template<class Ep>
__global__ void __launch_bounds__(256)
gemm_tf32(const float* __restrict__ A, const float* __restrict__ B,
          int M, int N, int K,
          const int* __restrict__ mcnt,   // if non-null: device row count (per z)
          const int* __restrict__ ridx,   // if non-null: gather A rows (per z)
          size_t aZ, size_t bZ, int listZ,
          Ep ep)
{
    constexpr int BM=128, BN=128, BK=32;
    constexpr int LDA=36, LDB=136;
    extern __shared__ float sm_[];
    float (*As)[BM][LDA] = reinterpret_cast<float(*)[BM][LDA]>(sm_);
    float (*Bs)[BK][LDB] = reinterpret_cast<float(*)[BK][LDB]>(sm_ + 2*BM*LDA);
    constexpr uint32_t A_STG = BM*LDA*4;   // bytes per A stage
    constexpr uint32_t B_STG = BK*LDB*4;   // bytes per B stage

    int e = blockIdx.z;
    A += (size_t)e*aZ;
    B += (size_t)e*bZ;
    if (mcnt) mcnt += e;
    if (ridx) ridx += (size_t)e*listZ;
    ep.setz(e);

    int Mr = mcnt ? *mcnt : M;
    int rb = blockIdx.y*BM;
    if (rb >= Mr) return;
    int nb = blockIdx.x*BN;

    int tid  = threadIdx.x;
    int lane = tid & 31, wid = tid >> 5;
    int wm = wid & 3, wn = wid >> 2;
    int g  = lane >> 2, tg = lane & 3;

    // A: thread covers one row, 16 floats starting at (tid&1)*16
    int a_row = tid >> 1;
    int a_k0  = (tid & 1) * 16;
    bool a_ok = (rb + a_row) < Mr;
    const float* a_src = A;
    if (a_ok) {
        int ar = ridx ? ridx[rb + a_row] : (rb + a_row);
        a_src = A + (size_t)ar*K + a_k0;
    }
    uint32_t a_dst0 = (uint32_t)__cvta_generic_to_shared(&As[0][a_row][a_k0]);

    // B: 4 chunks per thread, linear chunk id c = tid + 256*j
    const float* b_src[4]; bool b_ok[4]; uint32_t b_dst0[4];
    #pragma unroll
    for (int j=0;j<4;j++) {
        int c = tid + 256*j;
        int br = c >> 5;
        int bc = (c & 31) * 4;
        b_ok[j]  = (nb + bc) < N;
        b_src[j] = B + (size_t)br*N + nb + bc;
        b_dst0[j] = (uint32_t)__cvta_generic_to_shared(&Bs[0][br][bc]);
    }

    float4 acc[2][8];
    #pragma unroll
    for (int i=0;i<2;i++)
        #pragma unroll
        for (int j=0;j<8;j++) acc[i][j] = make_float4(0.f,0.f,0.f,0.f);

    int KT = K/BK;

    // prologue: tile 0 → stage 0
    #pragma unroll
    for (int q=0;q<4;q++) cpa16(a_dst0 + q*16, a_src + q*4, a_ok);
    #pragma unroll
    for (int j=0;j<4;j++) cpa16(b_dst0[j], b_src[j], b_ok[j]);
    cpa_commit();

    for (int kt=0; kt<KT; kt++) {
        int s = kt & 1;
        if (kt+1 < KT) {
            uint32_t ns = (uint32_t)((kt+1) & 1);
            const float* as = a_src + (size_t)(kt+1)*BK;
            #pragma unroll
            for (int q=0;q<4;q++) cpa16(a_dst0 + ns*A_STG + q*16, as + q*4, a_ok);
            size_t boff = (size_t)(kt+1)*BK*N;
            #pragma unroll
            for (int j=0;j<4;j++) cpa16(b_dst0[j] + ns*B_STG, b_src[j] + boff, b_ok[j]);
        }
        cpa_commit();
        cpa_wait1();          // tile kt resident; tile kt+1 may be in flight
        __syncthreads();

        #pragma unroll
        for (int ks=0; ks<BK; ks+=8) {
            uint32_t af[2][4];
            #pragma unroll
            for (int i=0;i<2;i++) {
                int m0 = wm*32 + i*16 + g;
                af[i][0] = tf32u(As[s][m0  ][ks+tg  ]);
                af[i][1] = tf32u(As[s][m0+8][ks+tg  ]);
                af[i][2] = tf32u(As[s][m0  ][ks+tg+4]);
                af[i][3] = tf32u(As[s][m0+8][ks+tg+4]);
            }
            uint32_t bf[8][2];
            #pragma unroll
            for (int j=0;j<8;j++) {
                int n0 = wn*64 + j*8 + g;
                bf[j][0] = tf32u(Bs[s][ks+tg  ][n0]);
                bf[j][1] = tf32u(Bs[s][ks+tg+4][n0]);
            }
            #pragma unroll
            for (int i=0;i<2;i++)
                #pragma unroll
                for (int j=0;j<8;j++) mma_tf32(acc[i][j], af[i], bf[j]);
        }
        __syncthreads();
    }

    #pragma unroll
    for (int i=0;i<2;i++) {
        int r0 = rb + wm*32 + i*16 + g;
        int r1 = r0 + 8;
        #pragma unroll
        for (int j=0;j<8;j++) {
            int c0 = nb + wn*64 + j*8 + tg*2;
            if (r0 < Mr) {
                if (c0   < N) ep.store(r0, c0,   acc[i][j].x);
                if (c0+1 < N) ep.store(r0, c0+1, acc[i][j].y);
            }
            if (r1 < Mr) {
                if (c0   < N) ep.store(r1, c0,   acc[i][j].z);
                if (c0+1 < N) ep.store(r1, c0+1, acc[i][j].w);
            }
        }
    }
}

// ---------------- concat dt|B|C weights into [INNER, 192] --------------------
__global__ void concat_dbc_kernel(const float* __restrict__ dtw,
                                  const float* __restrict__ bpw,
                                  const float* __restrict__ cpw,
                                  float* __restrict__ W)
{
    int i = blockIdx.x*blockDim.x + threadIdx.x;
    if (i >= INNER*NDBC) return;
    int r = i / NDBC, c = i % NDBC;
    float v;
    if (c < 64)       v = dtw[r*SST + c];
    else if (c < 128) v = bpw[r*SST + (c-64)];
    else              v = cpw[r*SST + (c-128)];
    W[i] = v;
}

// ---------------- rmsnorm (row of 1024), eps 1e-6 ----------------------------
__global__ void rmsnorm_kernel(const float* __restrict__ x, const float* __restrict__ w,
                               float* __restrict__ o)
{
    int r = blockIdx.x;
    const float* xr = x + (size_t)r*DD;
    float s = 0.f;
    for (int i=threadIdx.x; i<DD; i+=blockDim.x) { float v = xr[i]; s = fmaf(v,v,s); }
    #pragma unroll
    for (int off=16; off; off>>=1) s += __shfl_xor_sync(0xffffffffu, s, off);
    __shared__ float red[8];
    int wid = threadIdx.x>>5, lane = threadIdx.x&31;
    if (lane==0) red[wid]=s;
    __syncthreads();
    if (threadIdx.x==0) {
        float t=0.f;
        for (int i=0;i<(int)(blockDim.x>>5);i++) t += red[i];
        red[0] = rsqrtf(t/(float)DD + 1e-6f);
    }
    __syncthreads();
    float nr = red[0];
    float* orow = o + (size_t)r*DD;
    for (int i=threadIdx.x; i<DD; i+=blockDim.x) orow[i] = xr[i]*nr*w[i];
}

// ---------------- causal depthwise conv (K=3) + silu, 4-channel vectorized ---
__global__ void conv_silu_kernel(const float* __restrict__ xz, const float* __restrict__ cw,
                                 const float* __restrict__ cb, float* __restrict__ xm)
{
    int idx = blockIdx.x*blockDim.x + threadIdx.x;       // over MTOK*INNER/4
    if (idx >= MTOK*INNER/4) return;
    int c4  = idx & (INNER/4 - 1);                       // 512 groups
    int tok = idx >> 9;
    int t   = tok & (TT-1);
    int c   = c4*4;
    const float* base = xz + (size_t)tok*(2*INNER) + c;   // x_main half
    float4 zero = make_float4(0.f,0.f,0.f,0.f);
    float4 x0 = *reinterpret_cast<const float4*>(base);
    float4 x1 = (t>=1) ? *reinterpret_cast<const float4*>(base - 2*INNER) : zero;
    float4 x2 = (t>=2) ? *reinterpret_cast<const float4*>(base - 4*INNER) : zero;
    float4 w0 = *reinterpret_cast<const float4*>(cw + c*3);
    float4 w1 = *reinterpret_cast<const float4*>(cw + c*3 + 4);
    float4 w2 = *reinterpret_cast<const float4*>(cw + c*3 + 8);
    float4 bb = *reinterpret_cast<const float4*>(cb + c);
    float v0 = fmaf(w0.x,x2.x, fmaf(w0.y,x1.x, w0.z*x0.x)) + bb.x;
    float v1 = fmaf(w0.w,x2.y, fmaf(w1.x,x1.y, w1.y*x0.y)) + bb.y;
    float v2 = fmaf(w1.z,x2.z, fmaf(w1.w,x1.z, w2.x*x0.z)) + bb.z;
    float v3 = fmaf(w2.y,x2.w, fmaf(w2.z,x1.w, w2.w*x0.w)) + bb.w;
    float4 r;
    r.x = v0 * sigmoidf_(v0);
    r.y = v1 * sigmoidf_(v1);
    r.z = v2 * sigmoidf_(v2);
    r.w = v3 * sigmoidf_(v3);
    *reinterpret_cast<float4*>(xm + (size_t)tok*INNER + c) = r;
}

// ---------------- selective-state scan (serial over T) -----------------------
__global__ void scan_kernel(const float* __restrict__ dt, const float* __restrict__ Bv,
                            const float* __restrict__ Cv, float* __restrict__ y)
{
    int tid = threadIdx.x;          // 128 = NB * SST
    if (tid >= NB*SST) return;
    int b = tid >> 6, s = tid & 63;
    float st = 0.f;
    size_t off = ((size_t)b*TT)*SST + s;
    for (int t=0; t<TT; t++, off += SST) {
        float d = dt[off], bb = Bv[off], cc = Cv[off];
        st = fmaf(d, bb - st, st);           // (1-d)*st + d*b
        y[off] = cc*st;
    }
}

// ---------------- layernorm over 64 (one warp per token), eps 1e-5 -----------
__global__ void ln64_kernel(float* __restrict__ y)
{
    int gw = (blockIdx.x*blockDim.x + threadIdx.x) >> 5;
    if (gw >= MTOK) return;
    int lane = threadIdx.x & 31;
    float* r = y + (size_t)gw*SST;
    float v0 = r[lane], v1 = r[lane+32];
    float sum = v0 + v1;
    #pragma unroll
    for (int off=16; off; off>>=1) sum += __shfl_xor_sync(0xffffffffu, sum, off);
    float mu = sum * (1.0f/64.0f);
    float d0 = v0-mu, d1 = v1-mu;
    float vs = d0*d0 + d1*d1;
    #pragma unroll
    for (int off=16; off; off>>=1) vs += __shfl_xor_sync(0xffffffffu, vs, off);
    float nr = rsqrtf(vs*(1.0f/64.0f) + 1e-5f);
    r[lane]    = d0*nr;
    r[lane+32] = d1*nr;
}

// ---------------- gating: logits, top-2 softmax → dense weights --------------
__global__ void gate_kernel(const float* __restrict__ h2, const float* __restrict__ gw,
                            const float* __restrict__ gb, float* __restrict__ wfull)
{
    int gwarp = (blockIdx.x*blockDim.x + threadIdx.x) >> 5;
    if (gwarp >= MTOK) return;
    int lane = threadIdx.x & 31;
    float a0=0,a1=0,a2=0,a3=0;
    const float* hr = h2 + (size_t)gwarp*DD;
    for (int d=lane; d<DD; d+=32) {
        float h = hr[d];
        float4 w = *reinterpret_cast<const float4*>(gw + d*4);
        a0 = fmaf(h,w.x,a0); a1 = fmaf(h,w.y,a1);
        a2 = fmaf(h,w.z,a2); a3 = fmaf(h,w.w,a3);
    }
    #pragma unroll
    for (int off=16; off; off>>=1) {
        a0 += __shfl_xor_sync(0xffffffffu,a0,off);
        a1 += __shfl_xor_sync(0xffffffffu,a1,off);
        a2 += __shfl_xor_sync(0xffffffffu,a2,off);
        a3 += __shfl_xor_sync(0xffffffffu,a3,off);
    }
    if (lane==0) {
        float l[4] = {a0+gb[0], a1+gb[1], a2+gb[2], a3+gb[3]};
        int i0 = 0;
        for (int e=1;e<4;e++) if (l[e] > l[i0]) i0 = e;       // strict: earliest on tie
        int i1 = -1;
        for (int e=0;e<4;e++) if (e!=i0 && (i1<0 || l[e] > l[i1])) i1 = e;
        float e1 = expf(l[i1]-l[i0]);
        float p0 = 1.0f/(1.0f+e1);
        float p1 = e1/(1.0f+e1);
        float* wr = wfull + (size_t)gwarp*NE;
        wr[0]=0.f; wr[1]=0.f; wr[2]=0.f; wr[3]=0.f;
        wr[i0]=p0; wr[i1]=p1;
    }
}

// ---------------- deterministic per-expert token lists -----------------------
__global__ void build_lists_kernel(const float* __restrict__ wfull,
                                   int* __restrict__ idx, float* __restrict__ wl,
                                   int* __restrict__ cnt)
{
    int e = blockIdx.x;
    __shared__ int pref[1024];
    __shared__ int base;
    if (threadIdx.x==0) base = 0;
    __syncthreads();
    for (int chunk=0; chunk<MTOK/1024; chunk++) {
        int t = chunk*1024 + threadIdx.x;
        float w = wfull[(size_t)t*NE + e];
        int pred = (w > 0.f) ? 1 : 0;
        pref[threadIdx.x] = pred;
        __syncthreads();
        for (int off=1; off<1024; off<<=1) {
            int v = (threadIdx.x >= off) ? pref[threadIdx.x-off] : 0;
            __syncthreads();
            pref[threadIdx.x] += v;
            __syncthreads();
        }
        if (pred) {
            int pos = base + pref[threadIdx.x] - 1;
            idx[e*MTOK + pos] = t;
            wl [e*MTOK + pos] = w;
        }
        __syncthreads();
        if (threadIdx.x==0) base += pref[1023];
        __syncthreads();
    }
    if (threadIdx.x==0) cnt[e] = base;
}

// =============================================================================
extern "C" void kernel_launch(void* const* d_in, const int* in_sizes, int n_in,
                              void* d_out, int out_size)
{
    const float* x    = (const float*)d_in[0];
    const float* n1w  = (const float*)d_in[1];
    const float* n2w  = (const float*)d_in[2];
    const float* ipw  = (const float*)d_in[3];
    const float* ipb  = (const float*)d_in[4];
    const float* cw   = (const float*)d_in[5];
    const float* cb   = (const float*)d_in[6];
    const float* dtw  = (const float*)d_in[7];
    const float* dtb  = (const float*)d_in[8];
    const float* bpw  = (const float*)d_in[9];
    const float* bpb  = (const float*)d_in[10];
    const float* cpw  = (const float*)d_in[11];
    const float* cpb  = (const float*)d_in[12];
    const float* s2iw = (const float*)d_in[13];
    const float* s2ib = (const float*)d_in[14];
    const float* Dp   = (const float*)d_in[15];
    const float* ow   = (const float*)d_in[16];
    const float* obp  = (const float*)d_in[17];
    const float* gw   = (const float*)d_in[18];
    const float* gb   = (const float*)d_in[19];
    const float* ew1  = (const float*)d_in[20];
    const float* eb1  = (const float*)d_in[21];
    const float* ew2  = (const float*)d_in[22];
    const float* eb2  = (const float*)d_in[23];
    float* out = (float*)d_out;

    float *h1,*xz,*xm,*dt,*Bm,*Cm,*y,*u,*x2,*h2,*hid,*wfull,*wl,*wdbc;
    int *idx,*cnt;
    cudaGetSymbolAddress((void**)&h1,   g_h1);
    cudaGetSymbolAddress((void**)&xz,   g_xz);
    cudaGetSymbolAddress((void**)&xm,   g_xm);
    cudaGetSymbolAddress((void**)&dt,   g_dt);
    cudaGetSymbolAddress((void**)&Bm,   g_Bm);
    cudaGetSymbolAddress((void**)&Cm,   g_Cm);
    cudaGetSymbolAddress((void**)&y,    g_y);
    cudaGetSymbolAddress((void**)&u,    g_u);
    cudaGetSymbolAddress((void**)&x2,   g_x2);
    cudaGetSymbolAddress((void**)&h2,   g_h2);
    cudaGetSymbolAddress((void**)&hid,  g_hid);
    cudaGetSymbolAddress((void**)&wfull,g_wfull);
    cudaGetSymbolAddress((void**)&wl,   g_wl);
    cudaGetSymbolAddress((void**)&wdbc, g_wdbc);
    cudaGetSymbolAddress((void**)&idx,  g_idx);
    cudaGetSymbolAddress((void**)&cnt,  g_cnt);

    // opt-in SMEM for all gemm instantiations (idempotent)
    cudaFuncSetAttribute(gemm_tf32<EpBias>, cudaFuncAttributeMaxDynamicSharedMemorySize, GEMM_SMEM);
    cudaFuncSetAttribute(gemm_tf32<EpDBC>,  cudaFuncAttributeMaxDynamicSharedMemorySize, GEMM_SMEM);
    cudaFuncSetAttribute(gemm_tf32<EpS2I>,  cudaFuncAttributeMaxDynamicSharedMemorySize, GEMM_SMEM);
    cudaFuncSetAttribute(gemm_tf32<EpOut>,  cudaFuncAttributeMaxDynamicSharedMemorySize, GEMM_SMEM);
    cudaFuncSetAttribute(gemm_tf32<EpGelu>, cudaFuncAttributeMaxDynamicSharedMemorySize, GEMM_SMEM);
    cudaFuncSetAttribute(gemm_tf32<EpMoE2>, cudaFuncAttributeMaxDynamicSharedMemorySize, GEMM_SMEM);

    // ---- mixer ----
    concat_dbc_kernel<<<(INNER*NDBC + 255)/256, 256>>>(dtw, bpw, cpw, wdbc);
    rmsnorm_kernel<<<MTOK, 256>>>(x, n1w, h1);

    gemm_tf32<EpBias><<<dim3(2*INNER/128, MTOK/128, 1), 256, GEMM_SMEM>>>(
        h1, ipw, MTOK, 2*INNER, DD, nullptr, nullptr, 0, 0, 0,
        EpBias{ipb, xz, 2*INNER});

    conv_silu_kernel<<<(MTOK*INNER/4)/256, 256>>>(xz, cw, cb, xm);

    gemm_tf32<EpDBC><<<dim3(2, MTOK/128, 1), 256, GEMM_SMEM>>>(
        xm, wdbc, MTOK, NDBC, INNER, nullptr, nullptr, 0, 0, 0,
        EpDBC{dtb, bpb, cpb, dt, Bm, Cm});

    scan_kernel<<<1, 128>>>(dt, Bm, Cm, y);
    ln64_kernel<<<MTOK/4, 128>>>(y);

    gemm_tf32<EpS2I><<<dim3(INNER/128, MTOK/128, 1), 256, GEMM_SMEM>>>(
        y, s2iw, MTOK, INNER, SST, nullptr, nullptr, 0, 0, 0,
        EpS2I{s2ib, Dp, xm, xz, u});

    gemm_tf32<EpOut><<<dim3(DD/128, MTOK/128, 1), 256, GEMM_SMEM>>>(
        u, ow, MTOK, DD, INNER, nullptr, nullptr, 0, 0, 0,
        EpOut{obp, x, x2, out});

    // ---- MoE ----
    rmsnorm_kernel<<<MTOK, 256>>>(x2, n2w, h2);
    gate_kernel<<<MTOK/8, 256>>>(h2, gw, gb, wfull);
    build_lists_kernel<<<NE, 1024>>>(wfull, idx, wl, cnt);

    // all experts' up-projections in one launch (blockIdx.z = expert)
    gemm_tf32<EpGelu><<<dim3(HIDD/128, MTOK/128, NE), 256, GEMM_SMEM>>>(
        h2, ew1, MTOK, HIDD, DD,
        cnt, idx, /*aZ=*/0, /*bZ=*/(size_t)DD*HIDD, /*listZ=*/MTOK,
        EpGelu{eb1, hid, HIDD});

    // all experts' down-projections in one launch; atomic scatter-add
    gemm_tf32<EpMoE2><<<dim3(DD/128, MTOK/128, NE), 256, GEMM_SMEM>>>(
        hid, ew2, MTOK, DD, HIDD,
        cnt, nullptr, /*aZ=*/(size_t)MTOK*HIDD, /*bZ=*/(size_t)HIDD*DD, /*listZ=*/0,
        EpMoE2{eb2, idx, wl, out});
}

// round 17
// speedup vs baseline: 1.1344x; 1.0062x over previous
#include <cuda_runtime.h>
#include <math.h>
#include <stdint.h>

// Problem constants
#define MTOK  4096      // B*T tokens
#define DD    1024      // model dim
#define INNER 2048      // expanded dim
#define SST   64        // state dim
#define HIDD  4096      // expert hidden
#define NE    4         // experts
#define TT    2048      // seq len
#define NB    2         // batch
#define NDBC  192       // fused dt|B|C output width
#define KSPL  4         // dbc split-K parts

// ---------------- scratch (static device memory; no allocations) -------------
__device__ float g_h1 [(size_t)MTOK*DD];
__device__ float g_xz [(size_t)MTOK*2*INNER];
__device__ float g_xm [(size_t)MTOK*INNER];
__device__ float g_dt [(size_t)MTOK*SST];
__device__ float g_Bm [(size_t)MTOK*SST];
__device__ float g_Cm [(size_t)MTOK*SST];
__device__ float g_y  [(size_t)MTOK*SST];
__device__ float g_u  [(size_t)MTOK*INNER];
__device__ float g_x2 [(size_t)MTOK*DD];
__device__ float g_h2 [(size_t)MTOK*DD];
__device__ float g_hid[(size_t)NE*MTOK*HIDD];   // per-expert hidden slices
__device__ float g_wfull[(size_t)MTOK*NE];
__device__ float g_wdbc[(size_t)INNER*NDBC];
__device__ float g_dbcp[(size_t)KSPL*MTOK*NDBC]; // dbc split-K partials
__device__ int   g_idx[NE*MTOK];
__device__ float g_wl [NE*MTOK];
__device__ int   g_cnt[NE];

__device__ __forceinline__ float sigmoidf_(float v){ return 1.0f/(1.0f+expf(-v)); }

// round-to-nearest tf32 (RNA), as uint bits
__device__ __forceinline__ uint32_t tf32u(float x){
    uint32_t u; asm("cvt.rna.tf32.f32 %0, %1;" : "=r"(u) : "f"(x));
    return u;
}

__device__ __forceinline__ void mma_tf32(float4& d, const uint32_t* a, const uint32_t* b){
    asm volatile("mma.sync.aligned.m16n8k8.row.col.f32.tf32.tf32.f32 "
        "{%0,%1,%2,%3}, {%4,%5,%6,%7}, {%8,%9}, {%0,%1,%2,%3};"
        : "+f"(d.x), "+f"(d.y), "+f"(d.z), "+f"(d.w)
        : "r"(a[0]), "r"(a[1]), "r"(a[2]), "r"(a[3]), "r"(b[0]), "r"(b[1]));
}

// cp.async 16B with zero-fill when pred is false (src-size = 0)
__device__ __forceinline__ void cpa16(uint32_t dst, const void* src, bool pred){
    int sz = pred ? 16 : 0;
    asm volatile("cp.async.cg.shared.global [%0], [%1], 16, %2;\n"
                 :: "r"(dst), "l"(src), "r"(sz));
}
__device__ __forceinline__ void cpa_commit(){ asm volatile("cp.async.commit_group;\n"); }
__device__ __forceinline__ void cpa_wait0(){ asm volatile("cp.async.wait_group 0;\n"); }

// ---------------- epilogue functors (all outputs full fp32) -------------------
struct EpBias {
    const float* bias; float* C; int ldc;
    __device__ __forceinline__ void setz(int){}
    __device__ __forceinline__ void store(int r,int c,float acc) const {
        C[(size_t)r*ldc + c] = acc + bias[c];
    }
};
struct EpSplit {         // raw partial store for split-K (z = part)
    float* scr;
    __device__ __forceinline__ void setz(int e){ scr += (size_t)e*MTOK*NDBC; }
    __device__ __forceinline__ void store(int r,int c,float acc) const {
        scr[(size_t)r*NDBC + c] = acc;
    }
};
struct EpGelu {          // exact gelu, per-expert hid slice via setz
    const float* bias; float* C; int ldc;
    __device__ __forceinline__ void setz(int e){
        bias += (size_t)e*HIDD;
        C    += (size_t)e*MTOK*HIDD;
    }
    __device__ __forceinline__ void store(int r,int c,float acc) const {
        float v = acc + bias[c];
        C[(size_t)r*ldc + c] = 0.5f*v*(1.0f + erff(v*0.70710678118654752f));
    }
};
struct EpS2I {           // + s2i_b + D*x_main, * sigmoid(gate)
    const float* bias; const float* Dp; const float* xm; const float* xz; float* C;
    __device__ __forceinline__ void setz(int){}
    __device__ __forceinline__ void store(int r,int c,float acc) const {
        float v = acc + bias[c];
        v = fmaf(Dp[c], xm[(size_t)r*INNER + c], v);
        v *= sigmoidf_(xz[(size_t)r*(2*INNER) + INNER + c]);
        C[(size_t)r*INNER + c] = v;
    }
};
struct EpOut {           // + out_b + residual x ; dual store (x2 and d_out)
    const float* bias; const float* resid; float* C; float* out;
    __device__ __forceinline__ void setz(int){}
    __device__ __forceinline__ void store(int r,int c,float acc) const {
        float v = acc + bias[c] + resid[(size_t)r*DD + c];
        C[(size_t)r*DD + c] = v;
        out[(size_t)r*DD + c] = v;
    }
};
struct EpMoE2 {          // scatter: out[tok] += w * (acc + b2); atomic (2 adds/elem)
    const float* bias; const int* idx; const float* wl; float* out;
    __device__ __forceinline__ void setz(int e){
        bias += (size_t)e*DD;
        idx  += (size_t)e*MTOK;
        wl   += (size_t)e*MTOK;
    }
    __device__ __forceinline__ void store(int r,int c,float acc) const {
        int t = idx[r];
        atomicAdd(&out[(size_t)t*DD + c], wl[r]*(acc + bias[c]));
    }
};

// ---------------- tf32 tensor-core GEMM, 2-stage cp.async, BK=32 -------------
// A row-major, row stride lda (K = loop length only). B row-major [*,N].
// blockIdx.z slice: A += z*aZ, B += z*bZ (aZ used as k-offset for split-K).
// Single barrier per tile: wait -> sync -> issue(next) -> compute.
#define GEMM_SMEM 71680
template<class Ep>
__global__ void __launch_bounds__(256)
gemm_tf32(const float* __restrict__ A, const float* __restrict__ B,
          int M, int N, int K, int lda,
          const int* __restrict__ mcnt,   // if non-null: device row count (per z)
          const int* __restrict__ ridx,   // if non-null: gather A rows (per z)
          size_t aZ, size_t bZ, int listZ,
          Ep ep)
{
    constexpr int BM=128, BN=128, BK=32;
    constexpr int LDA=36, LDB=136;
    extern __shared__ float sm_[];
    float (*As)[BM][LDA] = reinterpret_cast<float(*)[BM][LDA]>(sm_);
    float (*Bs)[BK][LDB] = reinterpret_cast<float(*)[BK][LDB]>(sm_ + 2*BM*LDA);
    constexpr uint32_t A_STG = BM*LDA*4;   // bytes per A stage
    constexpr uint32_t B_STG = BK*LDB*4;   // bytes per B stage

    int e = blockIdx.z;
    A += (size_t)e*aZ;
    B += (size_t)e*bZ;
    if (mcnt) mcnt += e;
    if (ridx) ridx += (size_t)e*listZ;
    ep.setz(e);

    int Mr = mcnt ? *mcnt : M;
    int rb = blockIdx.y*BM;
    if (rb >= Mr) return;
    int nb = blockIdx.x*BN;

    int tid  = threadIdx.x;
    int lane = tid & 31, wid = tid >> 5;
    int wm = wid & 3, wn = wid >> 2;
    int g  = lane >> 2, tg = lane & 3;

    // A: thread covers one row, 16 floats starting at (tid&1)*16
    int a_row = tid >> 1;
    int a_k0  = (tid & 1) * 16;
    bool a_ok = (rb + a_row) < Mr;
    const float* a_src = A;
    if (a_ok) {
        int ar = ridx ? ridx[rb + a_row] : (rb + a_row);
        a_src = A + (size_t)ar*lda + a_k0;
    }
    uint32_t a_dst0 = (uint32_t)__cvta_generic_to_shared(&As[0][a_row][a_k0]);

    // B: 4 chunks per thread, linear chunk id c = tid + 256*j
    const float* b_src[4]; bool b_ok[4]; uint32_t b_dst0[4];
    #pragma unroll
    for (int j=0;j<4;j++) {
        int c = tid + 256*j;
        int br = c >> 5;
        int bc = (c & 31) * 4;
        b_ok[j]  = (nb + bc) < N;
        b_src[j] = B + (size_t)br*N + nb + bc;
        b_dst0[j] = (uint32_t)__cvta_generic_to_shared(&Bs[0][br][bc]);
    }

    float4 acc[2][8];
    #pragma unroll
    for (int i=0;i<2;i++)
        #pragma unroll
        for (int j=0;j<8;j++) acc[i][j] = make_float4(0.f,0.f,0.f,0.f);

    int KT = K/BK;

    // prologue: tile 0 -> stage 0
    #pragma unroll
    for (int q=0;q<4;q++) cpa16(a_dst0 + q*16, a_src + q*4, a_ok);
    #pragma unroll
    for (int j=0;j<4;j++) cpa16(b_dst0[j], b_src[j], b_ok[j]);
    cpa_commit();

    for (int kt=0; kt<KT; kt++) {
        int s = kt & 1;
        cpa_wait0();              // tile kt resident (own thread's copies)
        __syncthreads();          // visible to all; all warps done reading stage s^1
        if (kt+1 < KT) {          // issue tile kt+1 into stage s^1 (safe post-barrier)
            uint32_t ns = (uint32_t)((kt+1) & 1);
            const float* as = a_src + (size_t)(kt+1)*BK;
            #pragma unroll
            for (int q=0;q<4;q++) cpa16(a_dst0 + ns*A_STG + q*16, as + q*4, a_ok);
            size_t boff = (size_t)(kt+1)*BK*N;
            #pragma unroll
            for (int j=0;j<4;j++) cpa16(b_dst0[j] + ns*B_STG, b_src[j] + boff, b_ok[j]);
            cpa_commit();
        }

        #pragma unroll
        for (int ks=0; ks<BK; ks+=8) {
            uint32_t af[2][4];
            #pragma unroll
            for (int i=0;i<2;i++) {
                int m0 = wm*32 + i*16 + g;
                af[i][0] = tf32u(As[s][m0  ][ks+tg  ]);
                af[i][1] = tf32u(As[s][m0+8][ks+tg  ]);
                af[i][2] = tf32u(As[s][m0  ][ks+tg+4]);
                af[i][3] = tf32u(As[s][m0+8][ks+tg+4]);
            }
            uint32_t bf[8][2];
            #pragma unroll
            for (int j=0;j<8;j++) {
                int n0 = wn*64 + j*8 + g;
                bf[j][0] = tf32u(Bs[s][ks+tg  ][n0]);
                bf[j][1] = tf32u(Bs[s][ks+tg+4][n0]);
            }
            #pragma unroll
            for (int i=0;i<2;i++)
                #pragma unroll
                for (int j=0;j<8;j++) mma_tf32(acc[i][j], af[i], bf[j]);
        }
    }

    #pragma unroll
    for (int i=0;i<2;i++) {
        int r0 = rb + wm*32 + i*16 + g;
        int r1 = r0 + 8;
        #pragma unroll
        for (int j=0;j<8;j++) {
            int c0 = nb + wn*64 + j*8 + tg*2;
            if (r0 < Mr) {
                if (c0   < N) ep.store(r0, c0,   acc[i][j].x);
                if (c0+1 < N) ep.store(r0, c0+1, acc[i][j].y);
            }
            if (r1 < Mr) {
                if (c0   < N) ep.store(r1, c0,   acc[i][j].z);
                if (c0+1 < N) ep.store(r1, c0+1, acc[i][j].w);
            }
        }
    }
}

// ---------------- dbc split-K reduce: sum 4 partials, bias + route -----------
__global__ void dbc_reduce_kernel(const float* __restrict__ scr,
                                  const float* __restrict__ dtb,
                                  const float* __restrict__ bpb,
                                  const float* __restrict__ cpb,
                                  float* __restrict__ dt, float* __restrict__ Bm,
                                  float* __restrict__ Cm)
{
    int i = blockIdx.x*blockDim.x + threadIdx.x;
    if (i >= MTOK*NDBC) return;
    const size_t P = (size_t)MTOK*NDBC;
    float s = ((scr[i] + scr[i+P]) + scr[i+2*P]) + scr[i+3*P];
    int r = i / NDBC, c = i % NDBC;
    if (c < 64)       dt[(size_t)r*SST + c]       = sigmoidf_(s + dtb[c]);
    else if (c < 128) Bm[(size_t)r*SST + (c-64)]  = s + bpb[c-64];
    else              Cm[(size_t)r*SST + (c-128)] = s + cpb[c-128];
}

// ---------------- concat dt|B|C weights into [INNER, 192] --------------------
__global__ void concat_dbc_kernel(const float* __restrict__ dtw,
                                  const float* __restrict__ bpw,
                                  const float* __restrict__ cpw,
                                  float* __restrict__ W)
{
    int i = blockIdx.x*blockDim.x + threadIdx.x;
    if (i >= INNER*NDBC) return;
    int r = i / NDBC, c = i % NDBC;
    float v;
    if (c < 64)       v = dtw[r*SST + c];
    else if (c < 128) v = bpw[r*SST + (c-64)];
    else              v = cpw[r*SST + (c-128)];
    W[i] = v;
}

// ---------------- rmsnorm (row of 1024), eps 1e-6 ----------------------------
__global__ void rmsnorm_kernel(const float* __restrict__ x, const float* __restrict__ w,
                               float* __restrict__ o)
{
    int r = blockIdx.x;
    const float* xr = x + (size_t)r*DD;
    float s = 0.f;
    for (int i=threadIdx.x; i<DD; i+=blockDim.x) { float v = xr[i]; s = fmaf(v,v,s); }
    #pragma unroll
    for (int off=16; off; off>>=1) s += __shfl_xor_sync(0xffffffffu, s, off);
    __shared__ float red[8];
    int wid = threadIdx.x>>5, lane = threadIdx.x&31;
    if (lane==0) red[wid]=s;
    __syncthreads();
    if (threadIdx.x==0) {
        float t=0.f;
        for (int i=0;i<(int)(blockDim.x>>5);i++) t += red[i];
        red[0] = rsqrtf(t/(float)DD + 1e-6f);
    }
    __syncthreads();
    float nr = red[0];
    float* orow = o + (size_t)r*DD;
    for (int i=threadIdx.x; i<DD; i+=blockDim.x) orow[i] = xr[i]*nr*w[i];
}

// ---------------- causal depthwise conv (K=3) + silu, 4-channel vectorized ---
__global__ void conv_silu_kernel(const float* __restrict__ xz, const float* __restrict__ cw,
                                 const float* __restrict__ cb, float* __restrict__ xm)
{
    int idx = blockIdx.x*blockDim.x + threadIdx.x;       // over MTOK*INNER/4
    if (idx >= MTOK*INNER/4) return;
    int c4  = idx & (INNER/4 - 1);                       // 512 groups
    int tok = idx >> 9;
    int t   = tok & (TT-1);
    int c   = c4*4;
    const float* base = xz + (size_t)tok*(2*INNER) + c;   // x_main half
    float4 zero = make_float4(0.f,0.f,0.f,0.f);
    float4 x0 = *reinterpret_cast<const float4*>(base);
    float4 x1 = (t>=1) ? *reinterpret_cast<const float4*>(base - 2*INNER) : zero;
    float4 x2 = (t>=2) ? *reinterpret_cast<const float4*>(base - 4*INNER) : zero;
    float4 w0 = *reinterpret_cast<const float4*>(cw + c*3);
    float4 w1 = *reinterpret_cast<const float4*>(cw + c*3 + 4);
    float4 w2 = *reinterpret_cast<const float4*>(cw + c*3 + 8);
    float4 bb = *reinterpret_cast<const float4*>(cb + c);
    float v0 = fmaf(w0.x,x2.x, fmaf(w0.y,x1.x, w0.z*x0.x)) + bb.x;
    float v1 = fmaf(w0.w,x2.y, fmaf(w1.x,x1.y, w1.y*x0.y)) + bb.y;
    float v2 = fmaf(w1.z,x2.z, fmaf(w1.w,x1.z, w2.x*x0.z)) + bb.z;
    float v3 = fmaf(w2.y,x2.w, fmaf(w2.z,x1.w, w2.w*x0.w)) + bb.w;
    float4 r;
    r.x = v0 * sigmoidf_(v0);
    r.y = v1 * sigmoidf_(v1);
    r.z = v2 * sigmoidf_(v2);
    r.w = v3 * sigmoidf_(v3);
    *reinterpret_cast<float4*>(xm + (size_t)tok*INNER + c) = r;
}

// ---------------- selective-state scan (serial over T) -----------------------
__global__ void scan_kernel(const float* __restrict__ dt, const float* __restrict__ Bv,
                            const float* __restrict__ Cv, float* __restrict__ y)
{
    int tid = threadIdx.x;          // 128 = NB * SST
    if (tid >= NB*SST) return;
    int b = tid >> 6, s = tid & 63;
    float st = 0.f;
    size_t off = ((size_t)b*TT)*SST + s;
    for (int t=0; t<TT; t++, off += SST) {
        float d = dt[off], bb = Bv[off], cc = Cv[off];
        st = fmaf(d, bb - st, st);           // (1-d)*st + d*b
        y[off] = cc*st;
    }
}

// ---------------- layernorm over 64 (one warp per token), eps 1e-5 -----------
__global__ void ln64_kernel(float* __restrict__ y)
{
    int gw = (blockIdx.x*blockDim.x + threadIdx.x) >> 5;
    if (gw >= MTOK) return;
    int lane = threadIdx.x & 31;
    float* r = y + (size_t)gw*SST;
    float v0 = r[lane], v1 = r[lane+32];
    float sum = v0 + v1;
    #pragma unroll
    for (int off=16; off; off>>=1) sum += __shfl_xor_sync(0xffffffffu, sum, off);
    float mu = sum * (1.0f/64.0f);
    float d0 = v0-mu, d1 = v1-mu;
    float vs = d0*d0 + d1*d1;
    #pragma unroll
    for (int off=16; off; off>>=1) vs += __shfl_xor_sync(0xffffffffu, vs, off);
    float nr = rsqrtf(vs*(1.0f/64.0f) + 1e-5f);
    r[lane]    = d0*nr;
    r[lane+32] = d1*nr;
}

// ---------------- gating: logits, top-2 softmax → dense weights --------------
__global__ void gate_kernel(const float* __restrict__ h2, const float* __restrict__ gw,
                            const float* __restrict__ gb, float* __restrict__ wfull)
{
    int gwarp = (blockIdx.x*blockDim.x + threadIdx.x) >> 5;
    if (gwarp >= MTOK) return;
    int lane = threadIdx.x & 31;
    float a0=0,a1=0,a2=0,a3=0;
    const float* hr = h2 + (size_t)gwarp*DD;
    for (int d=lane; d<DD; d+=32) {
        float h = hr[d];
        float4 w = *reinterpret_cast<const float4*>(gw + d*4);
        a0 = fmaf(h,w.x,a0); a1 = fmaf(h,w.y,a1);
        a2 = fmaf(h,w.z,a2); a3 = fmaf(h,w.w,a3);
    }
    #pragma unroll
    for (int off=16; off; off>>=1) {
        a0 += __shfl_xor_sync(0xffffffffu,a0,off);
        a1 += __shfl_xor_sync(0xffffffffu,a1,off);
        a2 += __shfl_xor_sync(0xffffffffu,a2,off);
        a3 += __shfl_xor_sync(0xffffffffu,a3,off);
    }
    if (lane==0) {
        float l[4] = {a0+gb[0], a1+gb[1], a2+gb[2], a3+gb[3]};
        int i0 = 0;
        for (int e=1;e<4;e++) if (l[e] > l[i0]) i0 = e;       // strict: earliest on tie
        int i1 = -1;
        for (int e=0;e<4;e++) if (e!=i0 && (i1<0 || l[e] > l[i1])) i1 = e;
        float e1 = expf(l[i1]-l[i0]);
        float p0 = 1.0f/(1.0f+e1);
        float p1 = e1/(1.0f+e1);
        float* wr = wfull + (size_t)gwarp*NE;
        wr[0]=0.f; wr[1]=0.f; wr[2]=0.f; wr[3]=0.f;
        wr[i0]=p0; wr[i1]=p1;
    }
}

// ---------------- deterministic per-expert token lists -----------------------
__global__ void build_lists_kernel(const float* __restrict__ wfull,
                                   int* __restrict__ idx, float* __restrict__ wl,
                                   int* __restrict__ cnt)
{
    int e = blockIdx.x;
    __shared__ int pref[1024];
    __shared__ int base;
    if (threadIdx.x==0) base = 0;
    __syncthreads();
    for (int chunk=0; chunk<MTOK/1024; chunk++) {
        int t = chunk*1024 + threadIdx.x;
        float w = wfull[(size_t)t*NE + e];
        int pred = (w > 0.f) ? 1 : 0;
        pref[threadIdx.x] = pred;
        __syncthreads();
        for (int off=1; off<1024; off<<=1) {
            int v = (threadIdx.x >= off) ? pref[threadIdx.x-off] : 0;
            __syncthreads();
            pref[threadIdx.x] += v;
            __syncthreads();
        }
        if (pred) {
            int pos = base + pref[threadIdx.x] - 1;
            idx[e*MTOK + pos] = t;
            wl [e*MTOK + pos] = w;
        }
        __syncthreads();
        if (threadIdx.x==0) base += pref[1023];
        __syncthreads();
    }
    if (threadIdx.x==0) cnt[e] = base;
}

// =============================================================================
extern "C" void kernel_launch(void* const* d_in, const int* in_sizes, int n_in,
                              void* d_out, int out_size)
{
    const float* x    = (const float*)d_in[0];
    const float* n1w  = (const float*)d_in[1];
    const float* n2w  = (const float*)d_in[2];
    const float* ipw  = (const float*)d_in[3];
    const float* ipb  = (const float*)d_in[4];
    const float* cw   = (const float*)d_in[5];
    const float* cb   = (const float*)d_in[6];
    const float* dtw  = (const float*)d_in[7];
    const float* dtb  = (const float*)d_in[8];
    const float* bpw  = (const float*)d_in[9];
    const float* bpb  = (const float*)d_in[10];
    const float* cpw  = (const float*)d_in[11];
    const float* cpb  = (const float*)d_in[12];
    const float* s2iw = (const float*)d_in[13];
    const float* s2ib = (const float*)d_in[14];
    const float* Dp   = (const float*)d_in[15];
    const float* ow   = (const float*)d_in[16];
    const float* obp  = (const float*)d_in[17];
    const float* gw   = (const float*)d_in[18];
    const float* gb   = (const float*)d_in[19];
    const float* ew1  = (const float*)d_in[20];
    const float* eb1  = (const float*)d_in[21];
    const float* ew2  = (const float*)d_in[22];
    const float* eb2  = (const float*)d_in[23];
    float* out = (float*)d_out;

    float *h1,*xz,*xm,*dt,*Bm,*Cm,*y,*u,*x2,*h2,*hid,*wfull,*wl,*wdbc,*dbcp;
    int *idx,*cnt;
    cudaGetSymbolAddress((void**)&h1,   g_h1);
    cudaGetSymbolAddress((void**)&xz,   g_xz);
    cudaGetSymbolAddress((void**)&xm,   g_xm);
    cudaGetSymbolAddress((void**)&dt,   g_dt);
    cudaGetSymbolAddress((void**)&Bm,   g_Bm);
    cudaGetSymbolAddress((void**)&Cm,   g_Cm);
    cudaGetSymbolAddress((void**)&y,    g_y);
    cudaGetSymbolAddress((void**)&u,    g_u);
    cudaGetSymbolAddress((void**)&x2,   g_x2);
    cudaGetSymbolAddress((void**)&h2,   g_h2);
    cudaGetSymbolAddress((void**)&hid,  g_hid);
    cudaGetSymbolAddress((void**)&wfull,g_wfull);
    cudaGetSymbolAddress((void**)&wl,   g_wl);
    cudaGetSymbolAddress((void**)&wdbc, g_wdbc);
    cudaGetSymbolAddress((void**)&dbcp, g_dbcp);
    cudaGetSymbolAddress((void**)&idx,  g_idx);
    cudaGetSymbolAddress((void**)&cnt,  g_cnt);

    // opt-in SMEM for all gemm instantiations (idempotent)
    cudaFuncSetAttribute(gemm_tf32<EpBias>,  cudaFuncAttributeMaxDynamicSharedMemorySize, GEMM_SMEM);
    cudaFuncSetAttribute(gemm_tf32<EpSplit>, cudaFuncAttributeMaxDynamicSharedMemorySize, GEMM_SMEM);
    cudaFuncSetAttribute(gemm_tf32<EpS2I>,   cudaFuncAttributeMaxDynamicSharedMemorySize, GEMM_SMEM);
    cudaFuncSetAttribute(gemm_tf32<EpOut>,   cudaFuncAttributeMaxDynamicSharedMemorySize, GEMM_SMEM);
    cudaFuncSetAttribute(gemm_tf32<EpGelu>,  cudaFuncAttributeMaxDynamicSharedMemorySize, GEMM_SMEM);
    cudaFuncSetAttribute(gemm_tf32<EpMoE2>,  cudaFuncAttributeMaxDynamicSharedMemorySize, GEMM_SMEM);

    // ---- mixer ----
    concat_dbc_kernel<<<(INNER*NDBC + 255)/256, 256>>>(dtw, bpw, cpw, wdbc);
    rmsnorm_kernel<<<MTOK, 256>>>(x, n1w, h1);

    gemm_tf32<EpBias><<<dim3(2*INNER/128, MTOK/128, 1), 256, GEMM_SMEM>>>(
        h1, ipw, MTOK, 2*INNER, DD, DD, nullptr, nullptr, 0, 0, 0,
        EpBias{ipb, xz, 2*INNER});

    conv_silu_kernel<<<(MTOK*INNER/4)/256, 256>>>(xz, cw, cb, xm);

    // dbc: split-K over 4 parts of 512 (z = part; aZ = k-offset, bZ = row offset)
    gemm_tf32<EpSplit><<<dim3(2, MTOK/128, KSPL), 256, GEMM_SMEM>>>(
        xm, wdbc, MTOK, NDBC, INNER/KSPL, INNER, nullptr, nullptr,
        /*aZ=*/INNER/KSPL, /*bZ=*/(size_t)(INNER/KSPL)*NDBC, 0,
        EpSplit{dbcp});
    dbc_reduce_kernel<<<(MTOK*NDBC + 255)/256, 256>>>(dbcp, dtb, bpb, cpb, dt, Bm, Cm);

    scan_kernel<<<1, 128>>>(dt, Bm, Cm, y);
    ln64_kernel<<<MTOK/4, 128>>>(y);

    gemm_tf32<EpS2I><<<dim3(INNER/128, MTOK/128, 1), 256, GEMM_SMEM>>>(
        y, s2iw, MTOK, INNER, SST, SST, nullptr, nullptr, 0, 0, 0,
        EpS2I{s2ib, Dp, xm, xz, u});

    gemm_tf32<EpOut><<<dim3(DD/128, MTOK/128, 1), 256, GEMM_SMEM>>>(
        u, ow, MTOK, DD, INNER, INNER, nullptr, nullptr, 0, 0, 0,
        EpOut{obp, x, x2, out});

    // ---- MoE ----
    rmsnorm_kernel<<<MTOK, 256>>>(x2, n2w, h2);
    gate_kernel<<<MTOK/8, 256>>>(h2, gw, gb, wfull);
    build_lists_kernel<<<NE, 1024>>>(wfull, idx, wl, cnt);

    // all experts' up-projections in one launch (blockIdx.z = expert)
    gemm_tf32<EpGelu><<<dim3(HIDD/128, MTOK/128, NE), 256, GEMM_SMEM>>>(
        h2, ew1, MTOK, HIDD, DD, DD,
        cnt, idx, /*aZ=*/0, /*bZ=*/(size_t)DD*HIDD, /*listZ=*/MTOK,
        EpGelu{eb1, hid, HIDD});

    // all experts' down-projections in one launch; atomic scatter-add
    gemm_tf32<EpMoE2><<<dim3(DD/128, MTOK/128, NE), 256, GEMM_SMEM>>>(
        hid, ew2, MTOK, DD, HIDD, HIDD,
        cnt, nullptr, /*aZ=*/(size_t)MTOK*HIDD, /*bZ=*/(size_t)HIDD*DD, /*listZ=*/0,
        EpMoE2{eb2, idx, wl, out});
}